// round 6
// baseline (speedup 1.0000x reference)
#include <cuda_runtime.h>
#include <cuda_bf16.h>
#include <cstdint>

// Problem constants
#define TSTEPS 8
#define NB 64
#define NS 32
#define NBS 2048          // B*S
#define NK 3136           // DS == DT
#define NF 512
#define NH 512
#define NL 18
#define KSB 7             // split-K for basal GEMM
#define KCH_B 448         // 3136 / 7 (multiple of 32)
#define KSH 2             // split-K for h GEMM
#define KCH_H 256         // 512 / 2

// ---------------- scratch (__device__ globals; no allocation allowed) -------
__device__ float g_apical[TSTEPS * NBS * NF];        // 33.5 MB
__device__ float g_bpart[KSB * TSTEPS * NB * NF];
__device__ float g_mball[TSTEPS * NB * NF];          // precomputed mb(t)
__device__ float g_ma[NBS * NF];
__device__ float g_ms[NBS * NF];
__device__ __align__(16) __nv_bfloat16 g_sp16[NBS * NF];   // spikes (exact bf16)
__device__ float g_hpart[KSH * NBS * NH];
__device__ float g_ml[NBS * NH];
__device__ float g_acc[NBS * NL];
// bf16 hi/lo splits (weights only)
__device__ __align__(16) __nv_bfloat16 g_Wah[NF * NK];
__device__ __align__(16) __nv_bfloat16 g_Wal[NF * NK];
__device__ __align__(16) __nv_bfloat16 g_Wbh[NF * NK];
__device__ __align__(16) __nv_bfloat16 g_Wbl[NF * NK];
__device__ __align__(16) __nv_bfloat16 g_W1h[NH * NF];
__device__ __align__(16) __nv_bfloat16 g_W1l[NH * NF];

// ============================ PTX helpers ==================================
__device__ __forceinline__ uint32_t s2u(const void* p) {
    uint32_t a;
    asm("{ .reg .u64 t; cvta.to.shared.u64 t, %1; cvt.u32.u64 %0, t; }"
        : "=r"(a) : "l"(p));
    return a;
}
__device__ __forceinline__ void cp16(uint32_t s, const void* g) {
    asm volatile("cp.async.cg.shared.global [%0], [%1], 16;" :: "r"(s), "l"(g) : "memory");
}
__device__ __forceinline__ void cp_commit() {
    asm volatile("cp.async.commit_group;" ::: "memory");
}
__device__ __forceinline__ void cp_wait1() {
    asm volatile("cp.async.wait_group 1;" ::: "memory");
}
__device__ __forceinline__ void ldmx4(uint32_t* r, uint32_t a) {
    asm volatile("ldmatrix.sync.aligned.m8n8.x4.shared.b16 {%0,%1,%2,%3}, [%4];"
                 : "=r"(r[0]), "=r"(r[1]), "=r"(r[2]), "=r"(r[3]) : "r"(a));
}
__device__ __forceinline__ void hmma(float* c, const uint32_t* a, const uint32_t* b) {
    asm volatile(
        "mma.sync.aligned.m16n8k16.row.col.f32.bf16.bf16.f32 "
        "{%0,%1,%2,%3}, {%4,%5,%6,%7}, {%8,%9}, {%0,%1,%2,%3};"
        : "+f"(c[0]), "+f"(c[1]), "+f"(c[2]), "+f"(c[3])
        : "r"(a[0]), "r"(a[1]), "r"(a[2]), "r"(a[3]), "r"(b[0]), "r"(b[1]));
}

// split 4 fp32 -> packed bf16x2 hi pair + lo pair (RN split)
__device__ __forceinline__ void split4(float4 f, uint2& hi, uint2& lo) {
    __nv_bfloat16 h0 = __float2bfloat16(f.x), h1 = __float2bfloat16(f.y);
    __nv_bfloat16 h2 = __float2bfloat16(f.z), h3 = __float2bfloat16(f.w);
    __nv_bfloat162 H01 = __halves2bfloat162(h0, h1);
    __nv_bfloat162 H23 = __halves2bfloat162(h2, h3);
    __nv_bfloat162 L01 = __halves2bfloat162(
        __float2bfloat16(f.x - __bfloat162float(h0)),
        __float2bfloat16(f.y - __bfloat162float(h1)));
    __nv_bfloat162 L23 = __halves2bfloat162(
        __float2bfloat16(f.z - __bfloat162float(h2)),
        __float2bfloat16(f.w - __bfloat162float(h3)));
    hi.x = *(uint32_t*)&H01; hi.y = *(uint32_t*)&H23;
    lo.x = *(uint32_t*)&L01; lo.y = *(uint32_t*)&L23;
}

// ================= fused bf16-split HMMA GEMM ===============================
// MODE==3: A fp32 in gmem; producer LDGs fp32 and splits to (Ah, Al) bf16 in
//          smem in-kernel (half-interleaved with compute to cap live regs);
//          C = Ah*Bh^T + Ah*Bl^T + Al*Bh^T.
// MODE==2: A exact bf16 in gmem (spikes); C = A*Bh^T + A*Bl^T.
// B pre-split bf16 via cp.async. CTA 128x128, BK=32, 256 thr (8 warps 4Mx2N),
// 3-stage pipeline. blockIdx.z = K split; partial to C + z*M*Ntot.
#define BKT 32
#define NSTG 3

template<int MODE>
__global__ void __launch_bounds__(256, 2)
hmma_fused(const void* __restrict__ Araw,
           const __nv_bfloat16* __restrict__ Bh, const __nv_bfloat16* __restrict__ Bl,
           int kChunk, int lda, int Ntot, float* __restrict__ C, int M)
{
    extern __shared__ __nv_bfloat16 dsm[];
    constexpr int TILE   = 128 * BKT;
    constexpr int NTILES = (MODE == 3) ? 4 : 3;
    constexpr int STG    = NTILES * TILE;
    constexpr int OFF_AL = TILE;
    constexpr int OFF_BH = (MODE == 3) ? 2 * TILE : TILE;
    constexpr int OFF_BL = OFF_BH + TILE;

    const int tid  = threadIdx.x;
    const int wid  = tid >> 5;
    const int lane = tid & 31;
    const int wm   = wid & 3;
    const int wn   = wid >> 2;

    const int rowBase = blockIdx.y * 128;
    const int colBase = blockIdx.x * 128;
    const int kOff    = blockIdx.z * kChunk;
    const int NT      = kChunk / BKT;

    const uint32_t smemB = s2u(dsm);
    const float* A32        = (const float*)Araw;
    const __nv_bfloat16* A16 = (const __nv_bfloat16*)Araw;

    float acc[2][8][4];
#pragma unroll
    for (int mi = 0; mi < 2; mi++)
#pragma unroll
        for (int nj = 0; nj < 8; nj++)
#pragma unroll
            for (int q = 0; q < 4; q++) acc[mi][nj][q] = 0.f;

    // ---- B producer (cp.async, bf16 hi+lo) ----
    auto issueB = [&](int kt) {
        const int s  = kt % NSTG;
        const int kl = kt * BKT + kOff;
        const uint32_t base = smemB + (uint32_t)(s * STG) * 2;
#pragma unroll
        for (int i = 0; i < 2; i++) {
            const int v = tid + i * 256;
            const int m = v >> 2, u = v & 3;
            const uint32_t so = (uint32_t)(m * 64 + ((u ^ ((m >> 1) & 3)) << 4));
            const size_t gb = (size_t)(colBase + m) * lda + kl + u * 8;
            cp16(base + OFF_BH * 2 + so, Bh + gb);
            cp16(base + OFF_BL * 2 + so, Bl + gb);
        }
    };
    // ---- A producer, MODE2: exact bf16 via cp.async ----
    auto issueA2 = [&](int kt) {
        const int s  = kt % NSTG;
        const int kl = kt * BKT + kOff;
        const uint32_t base = smemB + (uint32_t)(s * STG) * 2;
#pragma unroll
        for (int i = 0; i < 2; i++) {
            const int v = tid + i * 256;
            const int m = v >> 2, u = v & 3;
            const uint32_t so = (uint32_t)(m * 64 + ((u ^ ((m >> 1) & 3)) << 4));
            cp16(base + so, A16 + (size_t)(rowBase + m) * lda + kl + u * 8);
        }
    };
    // ---- A producer, MODE3: half-granular LDG / split+STS (2 float4 each) --
    auto ldgA2 = [&](int kt, float4* f, int half) {
#pragma unroll
        for (int i = 0; i < 2; i++) {
            const int fv = tid + (half * 2 + i) * 256;    // 0..1023
            const int row = fv >> 3, u4 = fv & 7;
            f[i] = *(const float4*)(A32 + (size_t)(rowBase + row) * lda
                                    + kt * BKT + kOff + u4 * 4);
        }
    };
    auto stsA2 = [&](int kt, const float4* f, int half) {
        const int s = kt % NSTG;
        char* base = (char*)dsm + (size_t)(s * STG) * 2;
#pragma unroll
        for (int i = 0; i < 2; i++) {
            const int fv = tid + (half * 2 + i) * 256;
            const int row = fv >> 3, u4 = fv & 7;
            const int u = u4 >> 1, hf = u4 & 1;
            const uint32_t so = (uint32_t)(row * 64 + ((u ^ ((row >> 1) & 3)) << 4) + hf * 8);
            uint2 hi, lo;
            split4(f[i], hi, lo);
            *(uint2*)(base + so)              = hi;
            *(uint2*)(base + OFF_AL * 2 + so) = lo;
        }
    };

    // ---- one k16 half-stage of compute ----
    auto computeK16 = [&](int s, int k16) {
        const uint32_t base = smemB + (uint32_t)(s * STG) * 2;
        uint32_t ah[2][4], al[2][4];
#pragma unroll
        for (int mi = 0; mi < 2; mi++) {
            const int row = wm * 32 + mi * 16 + (lane & 15);
            const int u   = k16 * 2 + (lane >> 4);
            const uint32_t off = (uint32_t)(row * 64 + ((u ^ ((row >> 1) & 3)) << 4));
            ldmx4(ah[mi], base + off);
            if (MODE == 3) ldmx4(al[mi], base + OFF_AL * 2 + off);
        }
#pragma unroll
        for (int np = 0; np < 4; np++) {
            const int n = wn * 64 + np * 16 + ((lane >> 4) << 3) + (lane & 7);
            const int u = k16 * 2 + ((lane >> 3) & 1);
            const uint32_t boff = (uint32_t)(n * 64 + ((u ^ ((n >> 1) & 3)) << 4));
            uint32_t bh[4], bl[4];
            ldmx4(bh, base + OFF_BH * 2 + boff);
            ldmx4(bl, base + OFF_BL * 2 + boff);
#pragma unroll
            for (int mi = 0; mi < 2; mi++) {
                hmma(acc[mi][2 * np],     ah[mi], bh);
                hmma(acc[mi][2 * np + 1], ah[mi], bh + 2);
                hmma(acc[mi][2 * np],     ah[mi], bl);
                hmma(acc[mi][2 * np + 1], ah[mi], bl + 2);
                if (MODE == 3) {
                    hmma(acc[mi][2 * np],     al[mi], bh);
                    hmma(acc[mi][2 * np + 1], al[mi], bh + 2);
                }
            }
        }
    };

    // ---- prologue: fill stages 0,1 ----
    if (MODE == 3) {
        float4 f01[2], f23[2];
        ldgA2(0, f01, 0); ldgA2(0, f23, 1); stsA2(0, f01, 0); stsA2(0, f23, 1);
        issueB(0); cp_commit();
        if (NT > 1) {
            ldgA2(1, f01, 0); ldgA2(1, f23, 1); stsA2(1, f01, 0); stsA2(1, f23, 1);
            issueB(1);
        }
        cp_commit();
    } else {
        issueA2(0); issueB(0); cp_commit();
        if (NT > 1) { issueA2(1); issueB(1); }
        cp_commit();
    }
    cp_wait1();
    __syncthreads();

    // ---- mainloop ----
    for (int kt = 0; kt < NT; kt++) {
        const bool pf = (kt + 2 < NT);
        const int s = kt % NSTG;
        if (pf) { if (MODE == 2) issueA2(kt + 2); issueB(kt + 2); }
        cp_commit();
        float4 f01[2], f23[2];
        if (MODE == 3 && pf) ldgA2(kt + 2, f01, 0);       // 8 regs live
        computeK16(s, 0);
        if (MODE == 3 && pf) { ldgA2(kt + 2, f23, 1); stsA2(kt + 2, f01, 0); }
        computeK16(s, 1);
        if (MODE == 3 && pf) stsA2(kt + 2, f23, 1);
        cp_wait1();
        __syncthreads();
    }

    // ---- epilogue ----
    float* Cz = C + (size_t)blockIdx.z * M * Ntot;
#pragma unroll
    for (int mi = 0; mi < 2; mi++) {
        const int row = rowBase + wm * 32 + mi * 16 + (lane >> 2);
#pragma unroll
        for (int nj = 0; nj < 8; nj++) {
            const int col = colBase + wn * 64 + nj * 8 + (lane & 3) * 2;
            *(float2*)(Cz + (size_t)row * Ntot + col) =
                make_float2(acc[mi][nj][0], acc[mi][nj][1]);
            *(float2*)(Cz + (size_t)(row + 8) * Ntot + col) =
                make_float2(acc[mi][nj][2], acc[mi][nj][3]);
        }
    }
}

// =========================== small kernels ==================================
__global__ void split_bf16(const float* __restrict__ x,
                           __nv_bfloat16* __restrict__ hi,
                           __nv_bfloat16* __restrict__ lo, int n4)
{
    const int i = blockIdx.x * blockDim.x + threadIdx.x;
    if (i >= n4) return;
    float4 v = ((const float4*)x)[i];
    uint2 h, l;
    split4(v, h, l);
    ((uint2*)hi)[i] = h;
    ((uint2*)lo)[i] = l;
}

__global__ void init_state()
{
    const int i = blockIdx.x * blockDim.x + threadIdx.x;
    if (i < NBS * NF) { g_ma[i] = 0.f; g_ms[i] = 0.f; g_ml[i] = 0.f; }
    if (i < NBS * NL) g_acc[i] = 0.f;
}

// reduce basal split-K partials + precompute mb(t) recurrence in one pass
__global__ void reduce_basal_mb()
{
    const int i = blockIdx.x * blockDim.x + threadIdx.x;   // over NB*NF
    if (i >= NB * NF) return;
    float mb = 0.f;
#pragma unroll
    for (int t = 0; t < TSTEPS; t++) {
        const int e = t * NB * NF + i;
        float s = 0.f;
#pragma unroll
        for (int p = 0; p < KSB; p++) s += g_bpart[(size_t)p * (TSTEPS * NB * NF) + e];
        mb += (s - mb) * 0.5f;
        g_mball[e] = mb;
    }
}

// ---- mc_spike body (device fn shared by standalone + fused kernels) --------
__device__ __forceinline__ void mc_spike_body(int t, int i)
{
    const int e = i * 4;
    const int f = e & (NF - 1);
    const int b = e >> 14;
    float4 ap  = ((const float4*)(g_apical + (size_t)t * NBS * NF))[i];
    float4 mav = ((const float4*)g_ma)[i];
    float4 msv = ((const float4*)g_ms)[i];
    float4 mbv = *(const float4*)(g_mball + t * NB * NF + b * NF + f);
    float4 spv;

    mav.x += (ap.x - mav.x) * 0.5f;
    msv.x += (mav.x + mbv.x - msv.x) * 0.5f;
    spv.x = (msv.x > 1.0f) ? 1.f : 0.f;  msv.x *= (1.f - spv.x);

    mav.y += (ap.y - mav.y) * 0.5f;
    msv.y += (mav.y + mbv.y - msv.y) * 0.5f;
    spv.y = (msv.y > 1.0f) ? 1.f : 0.f;  msv.y *= (1.f - spv.y);

    mav.z += (ap.z - mav.z) * 0.5f;
    msv.z += (mav.z + mbv.z - msv.z) * 0.5f;
    spv.z = (msv.z > 1.0f) ? 1.f : 0.f;  msv.z *= (1.f - spv.z);

    mav.w += (ap.w - mav.w) * 0.5f;
    msv.w += (mav.w + mbv.w - msv.w) * 0.5f;
    spv.w = (msv.w > 1.0f) ? 1.f : 0.f;  msv.w *= (1.f - spv.w);

    ((float4*)g_ma)[i] = mav;
    ((float4*)g_ms)[i] = msv;
    __nv_bfloat162* sp = (__nv_bfloat162*)(g_sp16 + e);
    sp[0] = __halves2bfloat162(__float2bfloat16(spv.x), __float2bfloat16(spv.y));
    sp[1] = __halves2bfloat162(__float2bfloat16(spv.z), __float2bfloat16(spv.w));
}

__global__ void mc_spike(int t)
{
    const int i = blockIdx.x * blockDim.x + threadIdx.x;
    if (i < NBS * NF / 4) mc_spike_body(t, i);
}

// ---- lif_out body ----------------------------------------------------------
__device__ __forceinline__ void lif_out_body(const float* __restrict__ b1,
                                             const float* __restrict__ W2,
                                             int gw, int lane)
{
    float a[NL];
#pragma unroll
    for (int l = 0; l < NL; l++) a[l] = 0.f;
    const size_t base = (size_t)gw * NH;
#pragma unroll 4
    for (int j = 0; j < NH / 32; j++) {
        const int k = j * 32 + lane;
        const size_t idx = base + k;
        float h = b1[k] + g_hpart[idx] + g_hpart[(size_t)NBS * NH + idx];
        float m = g_ml[idx];
        m += (h - m) * 0.5f;
        const float s = (m > 0.5f) ? 1.f : 0.f;
        g_ml[idx] = m * (1.f - s);
        if (s != 0.f) {
#pragma unroll
            for (int l = 0; l < NL; l++) a[l] += W2[l * NH + k];
        }
    }
#pragma unroll
    for (int l = 0; l < NL; l++) {
#pragma unroll
        for (int o = 16; o; o >>= 1) a[l] += __shfl_xor_sync(0xffffffffu, a[l], o);
    }
    if (lane == 0) {
#pragma unroll
        for (int l = 0; l < NL; l++) g_acc[gw * NL + l] += a[l];
    }
}

// fused: lif_out for step t + mc_spike for step t+1 (independent data)
__global__ void lif_mc_fused(const float* __restrict__ b1,
                             const float* __restrict__ W2, int t)
{
    if (blockIdx.x < 256) {
        const int gw   = (blockIdx.x * blockDim.x + threadIdx.x) >> 5;
        const int lane = threadIdx.x & 31;
        lif_out_body(b1, W2, gw, lane);
    } else {
        const int i = (blockIdx.x - 256) * blockDim.x + threadIdx.x;
        if (i < NBS * NF / 4) mc_spike_body(t + 1, i);
    }
}

__global__ void lif_only(const float* __restrict__ b1, const float* __restrict__ W2)
{
    const int gw   = (blockIdx.x * blockDim.x + threadIdx.x) >> 5;
    const int lane = threadIdx.x & 31;
    if (gw < NBS) lif_out_body(b1, W2, gw, lane);
}

__global__ void finalize(const float* __restrict__ b2, float* __restrict__ out)
{
    const int i = blockIdx.x * blockDim.x + threadIdx.x;
    if (i >= NB * NL * NS) return;
    const int s = i % NS;
    const int l = (i / NS) % NL;
    const int b = i / (NS * NL);
    out[i] = g_acc[(b * NS + s) * NL + l] * (1.f / TSTEPS) + b2[l];
}

// ---------------------------------------------------------------------------
extern "C" void kernel_launch(void* const* d_in, const int* in_sizes, int n_in,
                              void* d_out, int out_size)
{
    (void)in_sizes; (void)n_in; (void)out_size;
    const float* se = (const float*)d_in[0];
    const float* te = (const float*)d_in[1];
    const float* Wb = (const float*)d_in[2];
    const float* Wa = (const float*)d_in[3];
    const float* W1 = (const float*)d_in[4];
    const float* b1 = (const float*)d_in[5];
    const float* W2 = (const float*)d_in[6];
    const float* b2 = (const float*)d_in[7];
    float* out = (float*)d_out;

    float *apical, *bpart, *hpart;
    __nv_bfloat16 *Wah, *Wal, *Wbh, *Wbl, *W1h, *W1l, *sp16;
    cudaGetSymbolAddress((void**)&apical, g_apical);
    cudaGetSymbolAddress((void**)&bpart,  g_bpart);
    cudaGetSymbolAddress((void**)&hpart,  g_hpart);
    cudaGetSymbolAddress((void**)&Wah,    g_Wah);
    cudaGetSymbolAddress((void**)&Wal,    g_Wal);
    cudaGetSymbolAddress((void**)&Wbh,    g_Wbh);
    cudaGetSymbolAddress((void**)&Wbl,    g_Wbl);
    cudaGetSymbolAddress((void**)&W1h,    g_W1h);
    cudaGetSymbolAddress((void**)&W1l,    g_W1l);
    cudaGetSymbolAddress((void**)&sp16,   g_sp16);

    const int SMEM3 = 4 * 128 * BKT * 2 * NSTG;   // 98304
    const int SMEM2 = 3 * 128 * BKT * 2 * NSTG;   // 73728
    cudaFuncSetAttribute(hmma_fused<3>, cudaFuncAttributeMaxDynamicSharedMemorySize, SMEM3);
    cudaFuncSetAttribute(hmma_fused<2>, cudaFuncAttributeMaxDynamicSharedMemorySize, SMEM2);

    // weight hi/lo splits only (te/se split in-kernel)
    split_bf16<<<(NF * NK / 4 + 255) / 256, 256>>>(Wa, Wah, Wal, NF * NK / 4);
    split_bf16<<<(NF * NK / 4 + 255) / 256, 256>>>(Wb, Wbh, Wbl, NF * NK / 4);
    split_bf16<<<(NH * NF / 4 + 255) / 256, 256>>>(W1, W1h, W1l, NH * NF / 4);

    init_state<<<(NBS * NF + 255) / 256, 256>>>();

    // basal: fp32-A fused-split HMMA, M=512 K=3136 N=512, split-K=7
    hmma_fused<3><<<dim3(NF / 128, (TSTEPS * NB) / 128, KSB), 256, SMEM3>>>(
        se, Wbh, Wbl, KCH_B, NK, NF, bpart, TSTEPS * NB);
    reduce_basal_mb<<<(NB * NF + 255) / 256, 256>>>();

    // apical: fp32-A fused-split HMMA, M=16384 N=512 K=3136, single sweep
    hmma_fused<3><<<dim3(NF / 128, (TSTEPS * NBS) / 128, 1), 256, SMEM3>>>(
        te, Wah, Wal, NK, NK, NF, apical, TSTEPS * NBS);

    mc_spike<<<(NBS * NF / 4 + 255) / 256, 256>>>(0);
    for (int t = 0; t < TSTEPS; t++) {
        // h = sp @ W1^T : sp exact bf16, W1 split => 2 products, split-K=2
        hmma_fused<2><<<dim3(NH / 128, NBS / 128, KSH), 256, SMEM2>>>(
            sp16, W1h, W1l, KCH_H, NF, NH, hpart, NBS);
        if (t < TSTEPS - 1)
            lif_mc_fused<<<256 + (NBS * NF / 4 + 255) / 256, 256>>>(b1, W2, t);
        else
            lif_only<<<256, 256>>>(b1, W2);
    }

    finalize<<<(NB * NL * NS + 255) / 256, 256>>>(b2, out);
}

// round 7
// speedup vs baseline: 1.1353x; 1.1353x over previous
#include <cuda_runtime.h>
#include <cuda_bf16.h>
#include <cstdint>

// Problem constants
#define TSTEPS 8
#define NB 64
#define NS 32
#define NBS 2048          // B*S
#define NK 3136           // DS == DT
#define NF 512
#define NH 512
#define NL 18
#define KSB 7             // split-K for basal GEMM
#define KCH_B 448         // 3136 / 7 (multiple of 32)
#define KSH 2             // split-K for h GEMM
#define KCH_H 256         // 512 / 2

// ---------------- scratch (__device__ globals; no allocation allowed) -------
__device__ float g_apical[TSTEPS * NBS * NF];        // 33.5 MB
__device__ float g_bpart[KSB * TSTEPS * NB * NF];
__device__ float g_mball[TSTEPS * NB * NF];          // precomputed mb(t)
__device__ float g_ma[NBS * NF];
__device__ float g_ms[NBS * NF];
__device__ __align__(16) __nv_bfloat16 g_sp16[NBS * NF];   // spikes (exact bf16)
__device__ float g_hpart[KSH * NBS * NH];
__device__ float g_ml[NBS * NH];
__device__ float g_acc[NBS * NL];
// bf16 hi/lo splits (weights only)
__device__ __align__(16) __nv_bfloat16 g_Wah[NF * NK];
__device__ __align__(16) __nv_bfloat16 g_Wal[NF * NK];
__device__ __align__(16) __nv_bfloat16 g_Wbh[NF * NK];
__device__ __align__(16) __nv_bfloat16 g_Wbl[NF * NK];
__device__ __align__(16) __nv_bfloat16 g_W1h[NH * NF];
__device__ __align__(16) __nv_bfloat16 g_W1l[NH * NF];

// ============================ PTX helpers ==================================
__device__ __forceinline__ uint32_t s2u(const void* p) {
    uint32_t a;
    asm("{ .reg .u64 t; cvta.to.shared.u64 t, %1; cvt.u32.u64 %0, t; }"
        : "=r"(a) : "l"(p));
    return a;
}
__device__ __forceinline__ void cp16(uint32_t s, const void* g) {
    asm volatile("cp.async.cg.shared.global [%0], [%1], 16;" :: "r"(s), "l"(g) : "memory");
}
__device__ __forceinline__ void cp_commit() {
    asm volatile("cp.async.commit_group;" ::: "memory");
}
__device__ __forceinline__ void cp_wait1() {
    asm volatile("cp.async.wait_group 1;" ::: "memory");
}
__device__ __forceinline__ void ldmx4(uint32_t* r, uint32_t a) {
    asm volatile("ldmatrix.sync.aligned.m8n8.x4.shared.b16 {%0,%1,%2,%3}, [%4];"
                 : "=r"(r[0]), "=r"(r[1]), "=r"(r[2]), "=r"(r[3]) : "r"(a));
}
__device__ __forceinline__ void hmma(float* c, const uint32_t* a, const uint32_t* b) {
    asm volatile(
        "mma.sync.aligned.m16n8k16.row.col.f32.bf16.bf16.f32 "
        "{%0,%1,%2,%3}, {%4,%5,%6,%7}, {%8,%9}, {%0,%1,%2,%3};"
        : "+f"(c[0]), "+f"(c[1]), "+f"(c[2]), "+f"(c[3])
        : "r"(a[0]), "r"(a[1]), "r"(a[2]), "r"(a[3]), "r"(b[0]), "r"(b[1]));
}

// split 4 fp32 -> packed bf16x2 hi pair + lo pair (RN split)
__device__ __forceinline__ void split4(float4 f, uint2& hi, uint2& lo) {
    __nv_bfloat16 h0 = __float2bfloat16(f.x), h1 = __float2bfloat16(f.y);
    __nv_bfloat16 h2 = __float2bfloat16(f.z), h3 = __float2bfloat16(f.w);
    __nv_bfloat162 H01 = __halves2bfloat162(h0, h1);
    __nv_bfloat162 H23 = __halves2bfloat162(h2, h3);
    __nv_bfloat162 L01 = __halves2bfloat162(
        __float2bfloat16(f.x - __bfloat162float(h0)),
        __float2bfloat16(f.y - __bfloat162float(h1)));
    __nv_bfloat162 L23 = __halves2bfloat162(
        __float2bfloat16(f.z - __bfloat162float(h2)),
        __float2bfloat16(f.w - __bfloat162float(h3)));
    hi.x = *(uint32_t*)&H01; hi.y = *(uint32_t*)&H23;
    lo.x = *(uint32_t*)&L01; lo.y = *(uint32_t*)&L23;
}

// ================= fused bf16-split HMMA GEMM ===============================
// MODE==3: A fp32 in gmem; producer LDGs fp32, splits to (Ah, Al) bf16 in smem
//          (R5-proven ordering: LDG batch -> compute -> STS batch);
//          C = Ah*Bh^T + Ah*Bl^T + Al*Bh^T.
// MODE==2: A exact bf16 in gmem (spikes); C = A*Bh^T + A*Bl^T.
// B pre-split bf16 via cp.async. CTA tile BM x 128, BK=32, 256 threads,
// 3-stage pipeline. blockIdx.z = K split; partial to C + z*M*Ntot.
// BM=64 cuts per-tile time in half to reduce wave quantization on big grids.
#define BKT 32
#define NSTG 3

template<int MODE, int BM>
__global__ void __launch_bounds__(256, 2)
hmma_fused(const void* __restrict__ Araw,
           const __nv_bfloat16* __restrict__ Bh, const __nv_bfloat16* __restrict__ Bl,
           int kChunk, int lda, int Ntot, float* __restrict__ C, int M)
{
    extern __shared__ __nv_bfloat16 dsm[];
    constexpr int TILE_A = BM * BKT;
    constexpr int TILE_B = 128 * BKT;
    constexpr int NTA    = (MODE == 3) ? 2 : 1;            // Ah,(Al)
    constexpr int STG    = NTA * TILE_A + 2 * TILE_B;
    constexpr int OFF_AL = TILE_A;
    constexpr int OFF_BH = NTA * TILE_A;
    constexpr int OFF_BL = OFF_BH + TILE_B;

    constexpr int WM   = BM / 32;        // M warp groups (4 or 2)
    constexpr int NCOL = 128 / (8 / WM); // cols per warp (64 or 32)
    constexpr int NJ   = NCOL / 8;       // 8 or 4
    constexpr int NP   = NCOL / 16;      // 4 or 2
    constexpr int AIT  = BM / 32;        // fp32 float4 loads per thread (4 or 2)

    const int tid  = threadIdx.x;
    const int wid  = tid >> 5;
    const int lane = tid & 31;
    const int wm   = wid & (WM - 1);
    const int wn   = wid / WM;

    const int rowBase = blockIdx.y * BM;
    const int colBase = blockIdx.x * 128;
    const int kOff    = blockIdx.z * kChunk;
    const int NT      = kChunk / BKT;

    const uint32_t smemB = s2u(dsm);
    const float* A32        = (const float*)Araw;
    const __nv_bfloat16* A16 = (const __nv_bfloat16*)Araw;

    float acc[2][NJ][4];
#pragma unroll
    for (int mi = 0; mi < 2; mi++)
#pragma unroll
        for (int nj = 0; nj < NJ; nj++)
#pragma unroll
            for (int q = 0; q < 4; q++) acc[mi][nj][q] = 0.f;

    // ---- B producer (cp.async, bf16 hi+lo; B always 128 rows) ----
    auto issueB = [&](int kt) {
        const int s  = kt % NSTG;
        const int kl = kt * BKT + kOff;
        const uint32_t base = smemB + (uint32_t)(s * STG) * 2;
#pragma unroll
        for (int i = 0; i < 2; i++) {
            const int v = tid + i * 256;
            const int m = v >> 2, u = v & 3;
            const uint32_t so = (uint32_t)(m * 64 + ((u ^ ((m >> 1) & 3)) << 4));
            const size_t gb = (size_t)(colBase + m) * lda + kl + u * 8;
            cp16(base + OFF_BH * 2 + so, Bh + gb);
            cp16(base + OFF_BL * 2 + so, Bl + gb);
        }
    };
    // ---- A producer, MODE2: exact bf16 via cp.async ----
    auto issueA2 = [&](int kt) {
        const int s  = kt % NSTG;
        const int kl = kt * BKT + kOff;
        const uint32_t base = smemB + (uint32_t)(s * STG) * 2;
#pragma unroll
        for (int i = 0; i < BM / 64; i++) {
            const int v = tid + i * 256;
            const int m = v >> 2, u = v & 3;
            const uint32_t so = (uint32_t)(m * 64 + ((u ^ ((m >> 1) & 3)) << 4));
            cp16(base + so, A16 + (size_t)(rowBase + m) * lda + kl + u * 8);
        }
    };
    // ---- A producer, MODE3: LDG fp32 into regs (R5 ordering) ----
    auto ldgA = [&](int kt, float4* f) {
#pragma unroll
        for (int i = 0; i < AIT; i++) {
            const int fv = tid + i * 256;                 // 0..BM*8-1
            const int row = fv >> 3, u4 = fv & 7;
            f[i] = *(const float4*)(A32 + (size_t)(rowBase + row) * lda
                                    + kt * BKT + kOff + u4 * 4);
        }
    };
    auto stsA = [&](int kt, const float4* f) {
        const int s = kt % NSTG;
        char* base = (char*)dsm + (size_t)(s * STG) * 2;
#pragma unroll
        for (int i = 0; i < AIT; i++) {
            const int fv = tid + i * 256;
            const int row = fv >> 3, u4 = fv & 7;
            const int u = u4 >> 1, half = u4 & 1;
            const uint32_t so = (uint32_t)(row * 64 + ((u ^ ((row >> 1) & 3)) << 4) + half * 8);
            uint2 hi, lo;
            split4(f[i], hi, lo);
            *(uint2*)(base + so)              = hi;
            *(uint2*)(base + OFF_AL * 2 + so) = lo;
        }
    };

    // ---- compute one BK=32 stage: all products ----
    auto compute = [&](int s) {
        const uint32_t base = smemB + (uint32_t)(s * STG) * 2;
#pragma unroll
        for (int k16 = 0; k16 < 2; k16++) {
            uint32_t ah[2][4], al[2][4];
#pragma unroll
            for (int mi = 0; mi < 2; mi++) {
                const int row = wm * 32 + mi * 16 + (lane & 15);
                const int u   = k16 * 2 + (lane >> 4);
                const uint32_t off = (uint32_t)(row * 64 + ((u ^ ((row >> 1) & 3)) << 4));
                ldmx4(ah[mi], base + off);
                if (MODE == 3) ldmx4(al[mi], base + OFF_AL * 2 + off);
            }
#pragma unroll
            for (int np = 0; np < NP; np++) {
                const int n = wn * NCOL + np * 16 + ((lane >> 4) << 3) + (lane & 7);
                const int u = k16 * 2 + ((lane >> 3) & 1);
                const uint32_t boff = (uint32_t)(n * 64 + ((u ^ ((n >> 1) & 3)) << 4));
                uint32_t bh[4], bl[4];
                ldmx4(bh, base + OFF_BH * 2 + boff);
                ldmx4(bl, base + OFF_BL * 2 + boff);
#pragma unroll
                for (int mi = 0; mi < 2; mi++) {
                    hmma(acc[mi][2 * np],     ah[mi], bh);
                    hmma(acc[mi][2 * np + 1], ah[mi], bh + 2);
                    hmma(acc[mi][2 * np],     ah[mi], bl);
                    hmma(acc[mi][2 * np + 1], ah[mi], bl + 2);
                    if (MODE == 3) {
                        hmma(acc[mi][2 * np],     al[mi], bh);
                        hmma(acc[mi][2 * np + 1], al[mi], bh + 2);
                    }
                }
            }
        }
    };

    // ---- prologue: fill stages 0,1 (R5 structure) ----
    float4 f[AIT];
    if (MODE == 3) { ldgA(0, f); stsA(0, f); } else { issueA2(0); }
    issueB(0); cp_commit();
    if (NT > 1) {
        if (MODE == 3) { ldgA(1, f); stsA(1, f); } else { issueA2(1); }
        issueB(1);
    }
    cp_commit();
    cp_wait1();
    __syncthreads();

    // ---- mainloop (R5-proven ordering) ----
    for (int kt = 0; kt < NT; kt++) {
        const bool pf = (kt + 2 < NT);
        if (MODE == 3 && pf) ldgA(kt + 2, f);        // LDG hidden under MMA
        if (pf) { if (MODE == 2) issueA2(kt + 2); issueB(kt + 2); }
        cp_commit();
        compute(kt % NSTG);
        if (MODE == 3 && pf) stsA(kt + 2, f);        // convert + store after MMA
        cp_wait1();
        __syncthreads();
    }

    // ---- epilogue ----
    float* Cz = C + (size_t)blockIdx.z * M * Ntot;
#pragma unroll
    for (int mi = 0; mi < 2; mi++) {
        const int row = rowBase + wm * 32 + mi * 16 + (lane >> 2);
#pragma unroll
        for (int nj = 0; nj < NJ; nj++) {
            const int col = colBase + wn * NCOL + nj * 8 + (lane & 3) * 2;
            *(float2*)(Cz + (size_t)row * Ntot + col) =
                make_float2(acc[mi][nj][0], acc[mi][nj][1]);
            *(float2*)(Cz + (size_t)(row + 8) * Ntot + col) =
                make_float2(acc[mi][nj][2], acc[mi][nj][3]);
        }
    }
}

// =========================== small kernels ==================================
__global__ void split_bf16(const float* __restrict__ x,
                           __nv_bfloat16* __restrict__ hi,
                           __nv_bfloat16* __restrict__ lo, int n4)
{
    const int i = blockIdx.x * blockDim.x + threadIdx.x;
    if (i >= n4) return;
    float4 v = ((const float4*)x)[i];
    uint2 h, l;
    split4(v, h, l);
    ((uint2*)hi)[i] = h;
    ((uint2*)lo)[i] = l;
}

__global__ void init_state()
{
    const int i = blockIdx.x * blockDim.x + threadIdx.x;
    if (i < NBS * NF) { g_ma[i] = 0.f; g_ms[i] = 0.f; g_ml[i] = 0.f; }
    if (i < NBS * NL) g_acc[i] = 0.f;
}

// reduce basal split-K partials + precompute mb(t) recurrence in one pass
__global__ void reduce_basal_mb()
{
    const int i = blockIdx.x * blockDim.x + threadIdx.x;   // over NB*NF
    if (i >= NB * NF) return;
    float mb = 0.f;
#pragma unroll
    for (int t = 0; t < TSTEPS; t++) {
        const int e = t * NB * NF + i;
        float s = 0.f;
#pragma unroll
        for (int p = 0; p < KSB; p++) s += g_bpart[(size_t)p * (TSTEPS * NB * NF) + e];
        mb += (s - mb) * 0.5f;
        g_mball[e] = mb;
    }
}

// ---- mc_spike body ---------------------------------------------------------
__device__ __forceinline__ void mc_spike_body(int t, int i)
{
    const int e = i * 4;
    const int f = e & (NF - 1);
    const int b = e >> 14;
    float4 ap  = ((const float4*)(g_apical + (size_t)t * NBS * NF))[i];
    float4 mav = ((const float4*)g_ma)[i];
    float4 msv = ((const float4*)g_ms)[i];
    float4 mbv = *(const float4*)(g_mball + t * NB * NF + b * NF + f);
    float4 spv;

    mav.x += (ap.x - mav.x) * 0.5f;
    msv.x += (mav.x + mbv.x - msv.x) * 0.5f;
    spv.x = (msv.x > 1.0f) ? 1.f : 0.f;  msv.x *= (1.f - spv.x);

    mav.y += (ap.y - mav.y) * 0.5f;
    msv.y += (mav.y + mbv.y - msv.y) * 0.5f;
    spv.y = (msv.y > 1.0f) ? 1.f : 0.f;  msv.y *= (1.f - spv.y);

    mav.z += (ap.z - mav.z) * 0.5f;
    msv.z += (mav.z + mbv.z - msv.z) * 0.5f;
    spv.z = (msv.z > 1.0f) ? 1.f : 0.f;  msv.z *= (1.f - spv.z);

    mav.w += (ap.w - mav.w) * 0.5f;
    msv.w += (mav.w + mbv.w - msv.w) * 0.5f;
    spv.w = (msv.w > 1.0f) ? 1.f : 0.f;  msv.w *= (1.f - spv.w);

    ((float4*)g_ma)[i] = mav;
    ((float4*)g_ms)[i] = msv;
    __nv_bfloat162* sp = (__nv_bfloat162*)(g_sp16 + e);
    sp[0] = __halves2bfloat162(__float2bfloat16(spv.x), __float2bfloat16(spv.y));
    sp[1] = __halves2bfloat162(__float2bfloat16(spv.z), __float2bfloat16(spv.w));
}

__global__ void mc_spike(int t)
{
    const int i = blockIdx.x * blockDim.x + threadIdx.x;
    if (i < NBS * NF / 4) mc_spike_body(t, i);
}

// ---- lif_out body ----------------------------------------------------------
__device__ __forceinline__ void lif_out_body(const float* __restrict__ b1,
                                             const float* __restrict__ W2,
                                             int gw, int lane)
{
    float a[NL];
#pragma unroll
    for (int l = 0; l < NL; l++) a[l] = 0.f;
    const size_t base = (size_t)gw * NH;
#pragma unroll 4
    for (int j = 0; j < NH / 32; j++) {
        const int k = j * 32 + lane;
        const size_t idx = base + k;
        float h = b1[k] + g_hpart[idx] + g_hpart[(size_t)NBS * NH + idx];
        float m = g_ml[idx];
        m += (h - m) * 0.5f;
        const float s = (m > 0.5f) ? 1.f : 0.f;
        g_ml[idx] = m * (1.f - s);
        if (s != 0.f) {
#pragma unroll
            for (int l = 0; l < NL; l++) a[l] += W2[l * NH + k];
        }
    }
#pragma unroll
    for (int l = 0; l < NL; l++) {
#pragma unroll
        for (int o = 16; o; o >>= 1) a[l] += __shfl_xor_sync(0xffffffffu, a[l], o);
    }
    if (lane == 0) {
#pragma unroll
        for (int l = 0; l < NL; l++) g_acc[gw * NL + l] += a[l];
    }
}

// fused: lif_out for step t + mc_spike for step t+1 (independent data)
__global__ void lif_mc_fused(const float* __restrict__ b1,
                             const float* __restrict__ W2, int t)
{
    if (blockIdx.x < 256) {
        const int gw   = (blockIdx.x * blockDim.x + threadIdx.x) >> 5;
        const int lane = threadIdx.x & 31;
        lif_out_body(b1, W2, gw, lane);
    } else {
        const int i = (blockIdx.x - 256) * blockDim.x + threadIdx.x;
        if (i < NBS * NF / 4) mc_spike_body(t + 1, i);
    }
}

__global__ void lif_only(const float* __restrict__ b1, const float* __restrict__ W2)
{
    const int gw   = (blockIdx.x * blockDim.x + threadIdx.x) >> 5;
    const int lane = threadIdx.x & 31;
    if (gw < NBS) lif_out_body(b1, W2, gw, lane);
}

__global__ void finalize(const float* __restrict__ b2, float* __restrict__ out)
{
    const int i = blockIdx.x * blockDim.x + threadIdx.x;
    if (i >= NB * NL * NS) return;
    const int s = i % NS;
    const int l = (i / NS) % NL;
    const int b = i / (NS * NL);
    out[i] = g_acc[(b * NS + s) * NL + l] * (1.f / TSTEPS) + b2[l];
}

// ---------------------------------------------------------------------------
extern "C" void kernel_launch(void* const* d_in, const int* in_sizes, int n_in,
                              void* d_out, int out_size)
{
    (void)in_sizes; (void)n_in; (void)out_size;
    const float* se = (const float*)d_in[0];
    const float* te = (const float*)d_in[1];
    const float* Wb = (const float*)d_in[2];
    const float* Wa = (const float*)d_in[3];
    const float* W1 = (const float*)d_in[4];
    const float* b1 = (const float*)d_in[5];
    const float* W2 = (const float*)d_in[6];
    const float* b2 = (const float*)d_in[7];
    float* out = (float*)d_out;

    float *apical, *bpart, *hpart;
    __nv_bfloat16 *Wah, *Wal, *Wbh, *Wbl, *W1h, *W1l, *sp16;
    cudaGetSymbolAddress((void**)&apical, g_apical);
    cudaGetSymbolAddress((void**)&bpart,  g_bpart);
    cudaGetSymbolAddress((void**)&hpart,  g_hpart);
    cudaGetSymbolAddress((void**)&Wah,    g_Wah);
    cudaGetSymbolAddress((void**)&Wal,    g_Wal);
    cudaGetSymbolAddress((void**)&Wbh,    g_Wbh);
    cudaGetSymbolAddress((void**)&Wbl,    g_Wbl);
    cudaGetSymbolAddress((void**)&W1h,    g_W1h);
    cudaGetSymbolAddress((void**)&W1l,    g_W1l);
    cudaGetSymbolAddress((void**)&sp16,   g_sp16);

    // smem: MODE3/BM64 stage = (2*64*32 + 2*128*32)*2B = 24KB; x3 = 73728
    //       MODE2/BM128 stage = (128*32 + 2*128*32)*2B = 24KB; x3 = 73728
    const int SMEM_M3 = (2 * 64 * BKT + 2 * 128 * BKT) * 2 * NSTG;   // 73728
    const int SMEM_M2 = (128 * BKT + 2 * 128 * BKT) * 2 * NSTG;      // 73728
    cudaFuncSetAttribute((const void*)hmma_fused<3, 64>,
                         cudaFuncAttributeMaxDynamicSharedMemorySize, SMEM_M3);
    cudaFuncSetAttribute((const void*)hmma_fused<2, 128>,
                         cudaFuncAttributeMaxDynamicSharedMemorySize, SMEM_M2);

    // weight hi/lo splits only (te/se split in-kernel)
    split_bf16<<<(NF * NK / 4 + 255) / 256, 256>>>(Wa, Wah, Wal, NF * NK / 4);
    split_bf16<<<(NF * NK / 4 + 255) / 256, 256>>>(Wb, Wbh, Wbl, NF * NK / 4);
    split_bf16<<<(NH * NF / 4 + 255) / 256, 256>>>(W1, W1h, W1l, NH * NF / 4);

    init_state<<<(NBS * NF + 255) / 256, 256>>>();

    // basal: fp32-A fused-split HMMA BM=64, M=512 K=3136 N=512, split-K=7
    hmma_fused<3, 64><<<dim3(NF / 128, (TSTEPS * NB) / 64, KSB), 256, SMEM_M3>>>(
        se, Wbh, Wbl, KCH_B, NK, NF, bpart, TSTEPS * NB);
    reduce_basal_mb<<<(NB * NF + 255) / 256, 256>>>();

    // apical: fp32-A fused-split HMMA BM=64, M=16384 N=512 K=3136 (1024 tiles)
    hmma_fused<3, 64><<<dim3(NF / 128, (TSTEPS * NBS) / 64, 1), 256, SMEM_M3>>>(
        te, Wah, Wal, NK, NK, NF, apical, TSTEPS * NBS);

    mc_spike<<<(NBS * NF / 4 + 255) / 256, 256>>>(0);
    for (int t = 0; t < TSTEPS; t++) {
        // h = sp @ W1^T : sp exact bf16, W1 split => 2 products, split-K=2
        hmma_fused<2, 128><<<dim3(NH / 128, NBS / 128, KSH), 256, SMEM_M2>>>(
            sp16, W1h, W1l, KCH_H, NF, NH, hpart, NBS);
        if (t < TSTEPS - 1)
            lif_mc_fused<<<256 + (NBS * NF / 4 + 255) / 256, 256>>>(b1, W2, t);
        else
            lif_only<<<256, 256>>>(b1, W2);
    }

    finalize<<<(NB * NL * NS + 255) / 256, 256>>>(b2, out);
}

// round 8
// speedup vs baseline: 1.3744x; 1.2106x over previous
#include <cuda_runtime.h>
#include <cuda_bf16.h>
#include <cstdint>

// Problem constants
#define TSTEPS 8
#define NB 64
#define NS 32
#define NBS 2048          // B*S
#define NK 3136           // DS == DT
#define NF 512
#define NH 512
#define NL 18
#define KSB 7             // split-K for basal GEMM
#define KCH_B 448         // 3136 / 7 (multiple of 32)

// ---------------- scratch (__device__ globals; no allocation allowed) -------
__device__ float g_apical[TSTEPS * NBS * NF];        // 33.5 MB
__device__ float g_bpart[KSB * TSTEPS * NB * NF];
__device__ float g_mball[TSTEPS * NB * NF];          // precomputed mb(t)
__device__ __align__(16) __nv_bfloat16 g_spall[TSTEPS * NBS * NF];  // all spikes
__device__ float g_hall[TSTEPS * NBS * NH];          // 67 MB
// bf16 hi/lo splits (weights only)
__device__ __align__(16) __nv_bfloat16 g_Wah[NF * NK];
__device__ __align__(16) __nv_bfloat16 g_Wal[NF * NK];
__device__ __align__(16) __nv_bfloat16 g_Wbh[NF * NK];
__device__ __align__(16) __nv_bfloat16 g_Wbl[NF * NK];
__device__ __align__(16) __nv_bfloat16 g_W1h[NH * NF];
__device__ __align__(16) __nv_bfloat16 g_W1l[NH * NF];

// ============================ PTX helpers ==================================
__device__ __forceinline__ uint32_t s2u(const void* p) {
    uint32_t a;
    asm("{ .reg .u64 t; cvta.to.shared.u64 t, %1; cvt.u32.u64 %0, t; }"
        : "=r"(a) : "l"(p));
    return a;
}
__device__ __forceinline__ void cp16(uint32_t s, const void* g) {
    asm volatile("cp.async.cg.shared.global [%0], [%1], 16;" :: "r"(s), "l"(g) : "memory");
}
__device__ __forceinline__ void cp_commit() {
    asm volatile("cp.async.commit_group;" ::: "memory");
}
__device__ __forceinline__ void cp_wait1() {
    asm volatile("cp.async.wait_group 1;" ::: "memory");
}
__device__ __forceinline__ void ldmx4(uint32_t* r, uint32_t a) {
    asm volatile("ldmatrix.sync.aligned.m8n8.x4.shared.b16 {%0,%1,%2,%3}, [%4];"
                 : "=r"(r[0]), "=r"(r[1]), "=r"(r[2]), "=r"(r[3]) : "r"(a));
}
__device__ __forceinline__ void hmma(float* c, const uint32_t* a, const uint32_t* b) {
    asm volatile(
        "mma.sync.aligned.m16n8k16.row.col.f32.bf16.bf16.f32 "
        "{%0,%1,%2,%3}, {%4,%5,%6,%7}, {%8,%9}, {%0,%1,%2,%3};"
        : "+f"(c[0]), "+f"(c[1]), "+f"(c[2]), "+f"(c[3])
        : "r"(a[0]), "r"(a[1]), "r"(a[2]), "r"(a[3]), "r"(b[0]), "r"(b[1]));
}

// split 4 fp32 -> packed bf16x2 hi pair + lo pair (RN split)
__device__ __forceinline__ void split4(float4 f, uint2& hi, uint2& lo) {
    __nv_bfloat16 h0 = __float2bfloat16(f.x), h1 = __float2bfloat16(f.y);
    __nv_bfloat16 h2 = __float2bfloat16(f.z), h3 = __float2bfloat16(f.w);
    __nv_bfloat162 H01 = __halves2bfloat162(h0, h1);
    __nv_bfloat162 H23 = __halves2bfloat162(h2, h3);
    __nv_bfloat162 L01 = __halves2bfloat162(
        __float2bfloat16(f.x - __bfloat162float(h0)),
        __float2bfloat16(f.y - __bfloat162float(h1)));
    __nv_bfloat162 L23 = __halves2bfloat162(
        __float2bfloat16(f.z - __bfloat162float(h2)),
        __float2bfloat16(f.w - __bfloat162float(h3)));
    hi.x = *(uint32_t*)&H01; hi.y = *(uint32_t*)&H23;
    lo.x = *(uint32_t*)&L01; lo.y = *(uint32_t*)&L23;
}

// ================= fused bf16-split HMMA GEMM ===============================
// MODE==3: A fp32 in gmem; producer LDGs fp32, splits to (Ah, Al) bf16 in smem
//          (R5-proven ordering); C = Ah*Bh^T + Ah*Bl^T + Al*Bh^T.
// MODE==2: A exact bf16 in gmem (spikes); C = A*Bh^T + A*Bl^T.
// B pre-split bf16 via cp.async. CTA tile BM x 128, BK=32, 256 threads,
// 3-stage pipeline. blockIdx.z = K split; partial to C + z*M*Ntot.
#define BKT 32
#define NSTG 3

template<int MODE, int BM>
__global__ void __launch_bounds__(256, 2)
hmma_fused(const void* __restrict__ Araw,
           const __nv_bfloat16* __restrict__ Bh, const __nv_bfloat16* __restrict__ Bl,
           int kChunk, int lda, int Ntot, float* __restrict__ C, int M)
{
    extern __shared__ __nv_bfloat16 dsm[];
    constexpr int TILE_A = BM * BKT;
    constexpr int TILE_B = 128 * BKT;
    constexpr int NTA    = (MODE == 3) ? 2 : 1;            // Ah,(Al)
    constexpr int STG    = NTA * TILE_A + 2 * TILE_B;
    constexpr int OFF_AL = TILE_A;
    constexpr int OFF_BH = NTA * TILE_A;
    constexpr int OFF_BL = OFF_BH + TILE_B;

    constexpr int WM   = BM / 32;        // M warp groups (2 for BM=64)
    constexpr int NCOL = 128 / (8 / WM); // cols per warp
    constexpr int NJ   = NCOL / 8;
    constexpr int NP   = NCOL / 16;
    constexpr int AIT  = BM / 32;        // fp32 float4 loads per thread

    const int tid  = threadIdx.x;
    const int wid  = tid >> 5;
    const int lane = tid & 31;
    const int wm   = wid & (WM - 1);
    const int wn   = wid / WM;

    const int rowBase = blockIdx.y * BM;
    const int colBase = blockIdx.x * 128;
    const int kOff    = blockIdx.z * kChunk;
    const int NT      = kChunk / BKT;

    const uint32_t smemB = s2u(dsm);
    const float* A32        = (const float*)Araw;
    const __nv_bfloat16* A16 = (const __nv_bfloat16*)Araw;

    float acc[2][NJ][4];
#pragma unroll
    for (int mi = 0; mi < 2; mi++)
#pragma unroll
        for (int nj = 0; nj < NJ; nj++)
#pragma unroll
            for (int q = 0; q < 4; q++) acc[mi][nj][q] = 0.f;

    // ---- B producer (cp.async, bf16 hi+lo; B always 128 rows) ----
    auto issueB = [&](int kt) {
        const int s  = kt % NSTG;
        const int kl = kt * BKT + kOff;
        const uint32_t base = smemB + (uint32_t)(s * STG) * 2;
#pragma unroll
        for (int i = 0; i < 2; i++) {
            const int v = tid + i * 256;
            const int m = v >> 2, u = v & 3;
            const uint32_t so = (uint32_t)(m * 64 + ((u ^ ((m >> 1) & 3)) << 4));
            const size_t gb = (size_t)(colBase + m) * lda + kl + u * 8;
            cp16(base + OFF_BH * 2 + so, Bh + gb);
            cp16(base + OFF_BL * 2 + so, Bl + gb);
        }
    };
    // ---- A producer, MODE2: exact bf16 via cp.async ----
    auto issueA2 = [&](int kt) {
        const int s  = kt % NSTG;
        const int kl = kt * BKT + kOff;
        const uint32_t base = smemB + (uint32_t)(s * STG) * 2;
#pragma unroll
        for (int i = 0; i < ((BM >= 64) ? BM / 64 : 1); i++) {
            const int v = tid + i * 256;
            const int m = v >> 2, u = v & 3;
            if (m < BM) {
                const uint32_t so = (uint32_t)(m * 64 + ((u ^ ((m >> 1) & 3)) << 4));
                cp16(base + so, A16 + (size_t)(rowBase + m) * lda + kl + u * 8);
            }
        }
    };
    // ---- A producer, MODE3: LDG fp32 into regs (R5 ordering) ----
    auto ldgA = [&](int kt, float4* f) {
#pragma unroll
        for (int i = 0; i < AIT; i++) {
            const int fv = tid + i * 256;
            const int row = fv >> 3, u4 = fv & 7;
            f[i] = *(const float4*)(A32 + (size_t)(rowBase + row) * lda
                                    + kt * BKT + kOff + u4 * 4);
        }
    };
    auto stsA = [&](int kt, const float4* f) {
        const int s = kt % NSTG;
        char* base = (char*)dsm + (size_t)(s * STG) * 2;
#pragma unroll
        for (int i = 0; i < AIT; i++) {
            const int fv = tid + i * 256;
            const int row = fv >> 3, u4 = fv & 7;
            const int u = u4 >> 1, half = u4 & 1;
            const uint32_t so = (uint32_t)(row * 64 + ((u ^ ((row >> 1) & 3)) << 4) + half * 8);
            uint2 hi, lo;
            split4(f[i], hi, lo);
            *(uint2*)(base + so)              = hi;
            *(uint2*)(base + OFF_AL * 2 + so) = lo;
        }
    };

    // ---- compute one BK=32 stage: all products ----
    auto compute = [&](int s) {
        const uint32_t base = smemB + (uint32_t)(s * STG) * 2;
#pragma unroll
        for (int k16 = 0; k16 < 2; k16++) {
            uint32_t ah[2][4], al[2][4];
#pragma unroll
            for (int mi = 0; mi < 2; mi++) {
                const int row = wm * 32 + mi * 16 + (lane & 15);
                const int u   = k16 * 2 + (lane >> 4);
                const uint32_t off = (uint32_t)(row * 64 + ((u ^ ((row >> 1) & 3)) << 4));
                ldmx4(ah[mi], base + off);
                if (MODE == 3) ldmx4(al[mi], base + OFF_AL * 2 + off);
            }
#pragma unroll
            for (int np = 0; np < NP; np++) {
                const int n = wn * NCOL + np * 16 + ((lane >> 4) << 3) + (lane & 7);
                const int u = k16 * 2 + ((lane >> 3) & 1);
                const uint32_t boff = (uint32_t)(n * 64 + ((u ^ ((n >> 1) & 3)) << 4));
                uint32_t bh[4], bl[4];
                ldmx4(bh, base + OFF_BH * 2 + boff);
                ldmx4(bl, base + OFF_BL * 2 + boff);
#pragma unroll
                for (int mi = 0; mi < 2; mi++) {
                    hmma(acc[mi][2 * np],     ah[mi], bh);
                    hmma(acc[mi][2 * np + 1], ah[mi], bh + 2);
                    hmma(acc[mi][2 * np],     ah[mi], bl);
                    hmma(acc[mi][2 * np + 1], ah[mi], bl + 2);
                    if (MODE == 3) {
                        hmma(acc[mi][2 * np],     al[mi], bh);
                        hmma(acc[mi][2 * np + 1], al[mi], bh + 2);
                    }
                }
            }
        }
    };

    // ---- prologue: fill stages 0,1 ----
    float4 f[AIT];
    if (MODE == 3) { ldgA(0, f); stsA(0, f); } else { issueA2(0); }
    issueB(0); cp_commit();
    if (NT > 1) {
        if (MODE == 3) { ldgA(1, f); stsA(1, f); } else { issueA2(1); }
        issueB(1);
    }
    cp_commit();
    cp_wait1();
    __syncthreads();

    // ---- mainloop (R5-proven ordering) ----
    for (int kt = 0; kt < NT; kt++) {
        const bool pf = (kt + 2 < NT);
        if (MODE == 3 && pf) ldgA(kt + 2, f);
        if (pf) { if (MODE == 2) issueA2(kt + 2); issueB(kt + 2); }
        cp_commit();
        compute(kt % NSTG);
        if (MODE == 3 && pf) stsA(kt + 2, f);
        cp_wait1();
        __syncthreads();
    }

    // ---- epilogue ----
    float* Cz = C + (size_t)blockIdx.z * M * Ntot;
#pragma unroll
    for (int mi = 0; mi < 2; mi++) {
        const int row = rowBase + wm * 32 + mi * 16 + (lane >> 2);
#pragma unroll
        for (int nj = 0; nj < NJ; nj++) {
            const int col = colBase + wn * NCOL + nj * 8 + (lane & 3) * 2;
            *(float2*)(Cz + (size_t)row * Ntot + col) =
                make_float2(acc[mi][nj][0], acc[mi][nj][1]);
            *(float2*)(Cz + (size_t)(row + 8) * Ntot + col) =
                make_float2(acc[mi][nj][2], acc[mi][nj][3]);
        }
    }
}

// =========================== small kernels ==================================
__global__ void split_bf16(const float* __restrict__ x,
                           __nv_bfloat16* __restrict__ hi,
                           __nv_bfloat16* __restrict__ lo, int n4)
{
    const int i = blockIdx.x * blockDim.x + threadIdx.x;
    if (i >= n4) return;
    float4 v = ((const float4*)x)[i];
    uint2 h, l;
    split4(v, h, l);
    ((uint2*)hi)[i] = h;
    ((uint2*)lo)[i] = l;
}

// reduce basal split-K partials + precompute mb(t) recurrence in one pass
__global__ void reduce_basal_mb()
{
    const int i = blockIdx.x * blockDim.x + threadIdx.x;   // over NB*NF
    if (i >= NB * NF) return;
    float mb = 0.f;
#pragma unroll
    for (int t = 0; t < TSTEPS; t++) {
        const int e = t * NB * NF + i;
        float s = 0.f;
#pragma unroll
        for (int p = 0; p < KSB; p++) s += g_bpart[(size_t)p * (TSTEPS * NB * NF) + e];
        mb += (s - mb) * 0.5f;
        g_mball[e] = mb;
    }
}

// ---- mc_all: whole MC-neuron time recurrence, elementwise, ONE launch ------
// ma/ms live in registers across all 8 steps; writes spikes for all t.
__global__ void mc_all()
{
    const int i = blockIdx.x * blockDim.x + threadIdx.x;   // over NBS*NF/4
    if (i >= NBS * NF / 4) return;
    const int e = i * 4;
    const int f = e & (NF - 1);
    const int b = e >> 14;                                 // e / (NS*NF)

    float4 mav = make_float4(0.f, 0.f, 0.f, 0.f);
    float4 msv = make_float4(0.f, 0.f, 0.f, 0.f);

#pragma unroll
    for (int t = 0; t < TSTEPS; t++) {
        float4 ap  = ((const float4*)(g_apical + (size_t)t * NBS * NF))[i];
        float4 mbv = *(const float4*)(g_mball + t * NB * NF + b * NF + f);
        float4 spv;

        mav.x += (ap.x - mav.x) * 0.5f;
        msv.x += (mav.x + mbv.x - msv.x) * 0.5f;
        spv.x = (msv.x > 1.0f) ? 1.f : 0.f;  msv.x *= (1.f - spv.x);

        mav.y += (ap.y - mav.y) * 0.5f;
        msv.y += (mav.y + mbv.y - msv.y) * 0.5f;
        spv.y = (msv.y > 1.0f) ? 1.f : 0.f;  msv.y *= (1.f - spv.y);

        mav.z += (ap.z - mav.z) * 0.5f;
        msv.z += (mav.z + mbv.z - msv.z) * 0.5f;
        spv.z = (msv.z > 1.0f) ? 1.f : 0.f;  msv.z *= (1.f - spv.z);

        mav.w += (ap.w - mav.w) * 0.5f;
        msv.w += (mav.w + mbv.w - msv.w) * 0.5f;
        spv.w = (msv.w > 1.0f) ? 1.f : 0.f;  msv.w *= (1.f - spv.w);

        __nv_bfloat162* sp = (__nv_bfloat162*)(g_spall + (size_t)t * NBS * NF + e);
        sp[0] = __halves2bfloat162(__float2bfloat16(spv.x), __float2bfloat16(spv.y));
        sp[1] = __halves2bfloat162(__float2bfloat16(spv.z), __float2bfloat16(spv.w));
    }
}

// ---- lif_all: LIF recurrence (ml in regs) + readout + finalize, ONE launch -
// One warp per row bs; ml[16] registers across all 8 steps; W2 readout
// accumulated over t; writes final out[b, l, s] = mean_t + b2.
__global__ void lif_all(const float* __restrict__ b1, const float* __restrict__ W2,
                        const float* __restrict__ b2, float* __restrict__ out)
{
    const int gw   = (blockIdx.x * blockDim.x + threadIdx.x) >> 5;  // row bs
    const int lane = threadIdx.x & 31;
    if (gw >= NBS) return;

    float ml[NH / 32];
#pragma unroll
    for (int j = 0; j < NH / 32; j++) ml[j] = 0.f;
    float a[NL];
#pragma unroll
    for (int l = 0; l < NL; l++) a[l] = 0.f;

    for (int t = 0; t < TSTEPS; t++) {
        const float* hrow = g_hall + ((size_t)t * NBS + gw) * NH;
#pragma unroll
        for (int j = 0; j < NH / 32; j++) {
            const int k = j * 32 + lane;
            const float h = b1[k] + hrow[k];
            float m = ml[j];
            m += (h - m) * 0.5f;
            const float s = (m > 0.5f) ? 1.f : 0.f;
            ml[j] = m * (1.f - s);
            if (s != 0.f) {
#pragma unroll
                for (int l = 0; l < NL; l++) a[l] += W2[l * NH + k];
            }
        }
    }
#pragma unroll
    for (int l = 0; l < NL; l++) {
#pragma unroll
        for (int o = 16; o; o >>= 1) a[l] += __shfl_xor_sync(0xffffffffu, a[l], o);
    }
    if (lane == 0) {
        const int b = gw >> 5;          // / NS
        const int sdx = gw & 31;        // % NS
#pragma unroll
        for (int l = 0; l < NL; l++)
            out[b * NL * NS + l * NS + sdx] = a[l] * (1.f / TSTEPS) + b2[l];
    }
}

// ---------------------------------------------------------------------------
extern "C" void kernel_launch(void* const* d_in, const int* in_sizes, int n_in,
                              void* d_out, int out_size)
{
    (void)in_sizes; (void)n_in; (void)out_size;
    const float* se = (const float*)d_in[0];
    const float* te = (const float*)d_in[1];
    const float* Wb = (const float*)d_in[2];
    const float* Wa = (const float*)d_in[3];
    const float* W1 = (const float*)d_in[4];
    const float* b1 = (const float*)d_in[5];
    const float* W2 = (const float*)d_in[6];
    const float* b2 = (const float*)d_in[7];
    float* out = (float*)d_out;

    float *apical, *bpart, *hall;
    __nv_bfloat16 *Wah, *Wal, *Wbh, *Wbl, *W1h, *W1l, *spall;
    cudaGetSymbolAddress((void**)&apical, g_apical);
    cudaGetSymbolAddress((void**)&bpart,  g_bpart);
    cudaGetSymbolAddress((void**)&hall,   g_hall);
    cudaGetSymbolAddress((void**)&Wah,    g_Wah);
    cudaGetSymbolAddress((void**)&Wal,    g_Wal);
    cudaGetSymbolAddress((void**)&Wbh,    g_Wbh);
    cudaGetSymbolAddress((void**)&Wbl,    g_Wbl);
    cudaGetSymbolAddress((void**)&W1h,    g_W1h);
    cudaGetSymbolAddress((void**)&W1l,    g_W1l);
    cudaGetSymbolAddress((void**)&spall,  g_spall);

    const int SMEM_M3 = (2 * 64 * BKT + 2 * 128 * BKT) * 2 * NSTG;   // 73728
    const int SMEM_M2 = (64 * BKT + 2 * 128 * BKT) * 2 * NSTG;       // 61440
    cudaFuncSetAttribute((const void*)hmma_fused<3, 64>,
                         cudaFuncAttributeMaxDynamicSharedMemorySize, SMEM_M3);
    cudaFuncSetAttribute((const void*)hmma_fused<2, 64>,
                         cudaFuncAttributeMaxDynamicSharedMemorySize, SMEM_M2);

    // weight hi/lo splits (te/se split in-kernel)
    split_bf16<<<(NF * NK / 4 + 255) / 256, 256>>>(Wa, Wah, Wal, NF * NK / 4);
    split_bf16<<<(NF * NK / 4 + 255) / 256, 256>>>(Wb, Wbh, Wbl, NF * NK / 4);
    split_bf16<<<(NH * NF / 4 + 255) / 256, 256>>>(W1, W1h, W1l, NH * NF / 4);

    // basal: fp32-A fused-split HMMA BM=64, split-K=7
    hmma_fused<3, 64><<<dim3(NF / 128, (TSTEPS * NB) / 64, KSB), 256, SMEM_M3>>>(
        se, Wbh, Wbl, KCH_B, NK, NF, bpart, TSTEPS * NB);
    reduce_basal_mb<<<(NB * NF + 255) / 256, 256>>>();

    // apical: fp32-A fused-split HMMA BM=64, M=16384 N=512 K=3136
    hmma_fused<3, 64><<<dim3(NF / 128, (TSTEPS * NBS) / 64, 1), 256, SMEM_M3>>>(
        te, Wah, Wal, NK, NK, NF, apical, TSTEPS * NBS);

    // MC neuron: all 8 steps in one elementwise pass (state in registers)
    mc_all<<<(NBS * NF / 4 + 255) / 256, 256>>>();

    // h for ALL steps: one batched GEMM, M=16384 K=512 N=512 (2 products)
    hmma_fused<2, 64><<<dim3(NH / 128, (TSTEPS * NBS) / 64, 1), 256, SMEM_M2>>>(
        spall, W1h, W1l, NF, NF, NH, hall, TSTEPS * NBS);

    // LIF + readout + finalize: one launch, ml in registers
    lif_all<<<(NBS * 32 + 255) / 256, 256>>>(b1, W2, b2, out);
}

// round 9
// speedup vs baseline: 1.3869x; 1.0091x over previous
#include <cuda_runtime.h>
#include <cuda_bf16.h>
#include <cstdint>

// Problem constants
#define TSTEPS 8
#define NB 64
#define NS 32
#define NBS 2048          // B*S
#define NK 3136           // DS == DT
#define NF 512
#define NH 512
#define NL 18
#define KSB 7             // split-K for basal GEMM
#define KCH_B 448         // 3136 / 7 (multiple of 32)

// ---------------- scratch (__device__ globals; no allocation allowed) -------
__device__ float g_apical[TSTEPS * NBS * NF];        // 33.5 MB
__device__ float g_bpart[KSB * TSTEPS * NB * NF];
__device__ float g_mball[TSTEPS * NB * NF];          // precomputed mb(t)
__device__ __align__(16) __nv_bfloat16 g_spall[TSTEPS * NBS * NF];  // all spikes
__device__ float g_hall[TSTEPS * NBS * NH];          // 67 MB
// bf16 hi/lo splits (weights only)
__device__ __align__(16) __nv_bfloat16 g_Wah[NF * NK];
__device__ __align__(16) __nv_bfloat16 g_Wal[NF * NK];
__device__ __align__(16) __nv_bfloat16 g_Wbh[NF * NK];
__device__ __align__(16) __nv_bfloat16 g_Wbl[NF * NK];
__device__ __align__(16) __nv_bfloat16 g_W1h[NH * NF];
__device__ __align__(16) __nv_bfloat16 g_W1l[NH * NF];

// ============================ PTX helpers ==================================
__device__ __forceinline__ uint32_t s2u(const void* p) {
    uint32_t a;
    asm("{ .reg .u64 t; cvta.to.shared.u64 t, %1; cvt.u32.u64 %0, t; }"
        : "=r"(a) : "l"(p));
    return a;
}
__device__ __forceinline__ void cp16(uint32_t s, const void* g) {
    asm volatile("cp.async.cg.shared.global [%0], [%1], 16;" :: "r"(s), "l"(g) : "memory");
}
__device__ __forceinline__ void cp_commit() {
    asm volatile("cp.async.commit_group;" ::: "memory");
}
__device__ __forceinline__ void cp_wait2() {
    asm volatile("cp.async.wait_group 2;" ::: "memory");
}
__device__ __forceinline__ void ldmx4(uint32_t* r, uint32_t a) {
    asm volatile("ldmatrix.sync.aligned.m8n8.x4.shared.b16 {%0,%1,%2,%3}, [%4];"
                 : "=r"(r[0]), "=r"(r[1]), "=r"(r[2]), "=r"(r[3]) : "r"(a));
}
__device__ __forceinline__ void hmma(float* c, const uint32_t* a, const uint32_t* b) {
    asm volatile(
        "mma.sync.aligned.m16n8k16.row.col.f32.bf16.bf16.f32 "
        "{%0,%1,%2,%3}, {%4,%5,%6,%7}, {%8,%9}, {%0,%1,%2,%3};"
        : "+f"(c[0]), "+f"(c[1]), "+f"(c[2]), "+f"(c[3])
        : "r"(a[0]), "r"(a[1]), "r"(a[2]), "r"(a[3]), "r"(b[0]), "r"(b[1]));
}

// split 4 fp32 -> packed bf16x2 hi pair + lo pair (RN split)
__device__ __forceinline__ void split4(float4 f, uint2& hi, uint2& lo) {
    __nv_bfloat16 h0 = __float2bfloat16(f.x), h1 = __float2bfloat16(f.y);
    __nv_bfloat16 h2 = __float2bfloat16(f.z), h3 = __float2bfloat16(f.w);
    __nv_bfloat162 H01 = __halves2bfloat162(h0, h1);
    __nv_bfloat162 H23 = __halves2bfloat162(h2, h3);
    __nv_bfloat162 L01 = __halves2bfloat162(
        __float2bfloat16(f.x - __bfloat162float(h0)),
        __float2bfloat16(f.y - __bfloat162float(h1)));
    __nv_bfloat162 L23 = __halves2bfloat162(
        __float2bfloat16(f.z - __bfloat162float(h2)),
        __float2bfloat16(f.w - __bfloat162float(h3)));
    hi.x = *(uint32_t*)&H01; hi.y = *(uint32_t*)&H23;
    lo.x = *(uint32_t*)&L01; lo.y = *(uint32_t*)&L23;
}

// ================= fused bf16-split HMMA GEMM ===============================
// MODE==3: A fp32 in gmem; producer LDGs fp32, splits to (Ah, Al) bf16 in smem
//          (R5-proven ordering); C = Ah*Bh^T + Ah*Bl^T + Al*Bh^T.
// MODE==2: A exact bf16 in gmem (spikes); C = A*Bh^T + A*Bl^T.
// B pre-split bf16 via cp.async. CTA tile BM x 128, BK=32, 256 threads,
// 4-stage pipeline, prefetch distance 3, wait_group 2.
// blockIdx.z = K split; partial to C + z*M*Ntot.
#define BKT 32
#define NSTG 4

template<int MODE, int BM>
__global__ void __launch_bounds__(256, 2)
hmma_fused(const void* __restrict__ Araw,
           const __nv_bfloat16* __restrict__ Bh, const __nv_bfloat16* __restrict__ Bl,
           int kChunk, int lda, int Ntot, float* __restrict__ C, int M)
{
    extern __shared__ __nv_bfloat16 dsm[];
    constexpr int TILE_A = BM * BKT;
    constexpr int TILE_B = 128 * BKT;
    constexpr int NTA    = (MODE == 3) ? 2 : 1;            // Ah,(Al)
    constexpr int STG    = NTA * TILE_A + 2 * TILE_B;
    constexpr int OFF_AL = TILE_A;
    constexpr int OFF_BH = NTA * TILE_A;
    constexpr int OFF_BL = OFF_BH + TILE_B;

    constexpr int WM   = BM / 32;        // M warp groups (2 for BM=64)
    constexpr int NCOL = 128 / (8 / WM); // cols per warp
    constexpr int NJ   = NCOL / 8;
    constexpr int NP   = NCOL / 16;
    constexpr int AIT  = BM / 32;        // fp32 float4 loads per thread

    const int tid  = threadIdx.x;
    const int wid  = tid >> 5;
    const int lane = tid & 31;
    const int wm   = wid & (WM - 1);
    const int wn   = wid / WM;

    const int rowBase = blockIdx.y * BM;
    const int colBase = blockIdx.x * 128;
    const int kOff    = blockIdx.z * kChunk;
    const int NT      = kChunk / BKT;

    const uint32_t smemB = s2u(dsm);
    const float* A32        = (const float*)Araw;
    const __nv_bfloat16* A16 = (const __nv_bfloat16*)Araw;

    float acc[2][NJ][4];
#pragma unroll
    for (int mi = 0; mi < 2; mi++)
#pragma unroll
        for (int nj = 0; nj < NJ; nj++)
#pragma unroll
            for (int q = 0; q < 4; q++) acc[mi][nj][q] = 0.f;

    // ---- B producer (cp.async, bf16 hi+lo; B always 128 rows) ----
    auto issueB = [&](int kt) {
        const int s  = kt % NSTG;
        const int kl = kt * BKT + kOff;
        const uint32_t base = smemB + (uint32_t)(s * STG) * 2;
#pragma unroll
        for (int i = 0; i < 2; i++) {
            const int v = tid + i * 256;
            const int m = v >> 2, u = v & 3;
            const uint32_t so = (uint32_t)(m * 64 + ((u ^ ((m >> 1) & 3)) << 4));
            const size_t gb = (size_t)(colBase + m) * lda + kl + u * 8;
            cp16(base + OFF_BH * 2 + so, Bh + gb);
            cp16(base + OFF_BL * 2 + so, Bl + gb);
        }
    };
    // ---- A producer, MODE2: exact bf16 via cp.async ----
    auto issueA2 = [&](int kt) {
        const int s  = kt % NSTG;
        const int kl = kt * BKT + kOff;
        const uint32_t base = smemB + (uint32_t)(s * STG) * 2;
#pragma unroll
        for (int i = 0; i < ((BM >= 64) ? BM / 64 : 1); i++) {
            const int v = tid + i * 256;
            const int m = v >> 2, u = v & 3;
            if (m < BM) {
                const uint32_t so = (uint32_t)(m * 64 + ((u ^ ((m >> 1) & 3)) << 4));
                cp16(base + so, A16 + (size_t)(rowBase + m) * lda + kl + u * 8);
            }
        }
    };
    // ---- A producer, MODE3: LDG fp32 into regs (R5 ordering) ----
    auto ldgA = [&](int kt, float4* f) {
#pragma unroll
        for (int i = 0; i < AIT; i++) {
            const int fv = tid + i * 256;
            const int row = fv >> 3, u4 = fv & 7;
            f[i] = *(const float4*)(A32 + (size_t)(rowBase + row) * lda
                                    + kt * BKT + kOff + u4 * 4);
        }
    };
    auto stsA = [&](int kt, const float4* f) {
        const int s = kt % NSTG;
        char* base = (char*)dsm + (size_t)(s * STG) * 2;
#pragma unroll
        for (int i = 0; i < AIT; i++) {
            const int fv = tid + i * 256;
            const int row = fv >> 3, u4 = fv & 7;
            const int u = u4 >> 1, half = u4 & 1;
            const uint32_t so = (uint32_t)(row * 64 + ((u ^ ((row >> 1) & 3)) << 4) + half * 8);
            uint2 hi, lo;
            split4(f[i], hi, lo);
            *(uint2*)(base + so)              = hi;
            *(uint2*)(base + OFF_AL * 2 + so) = lo;
        }
    };

    // ---- compute one BK=32 stage: all products ----
    auto compute = [&](int s) {
        const uint32_t base = smemB + (uint32_t)(s * STG) * 2;
#pragma unroll
        for (int k16 = 0; k16 < 2; k16++) {
            uint32_t ah[2][4], al[2][4];
#pragma unroll
            for (int mi = 0; mi < 2; mi++) {
                const int row = wm * 32 + mi * 16 + (lane & 15);
                const int u   = k16 * 2 + (lane >> 4);
                const uint32_t off = (uint32_t)(row * 64 + ((u ^ ((row >> 1) & 3)) << 4));
                ldmx4(ah[mi], base + off);
                if (MODE == 3) ldmx4(al[mi], base + OFF_AL * 2 + off);
            }
#pragma unroll
            for (int np = 0; np < NP; np++) {
                const int n = wn * NCOL + np * 16 + ((lane >> 4) << 3) + (lane & 7);
                const int u = k16 * 2 + ((lane >> 3) & 1);
                const uint32_t boff = (uint32_t)(n * 64 + ((u ^ ((n >> 1) & 3)) << 4));
                uint32_t bh[4], bl[4];
                ldmx4(bh, base + OFF_BH * 2 + boff);
                ldmx4(bl, base + OFF_BL * 2 + boff);
#pragma unroll
                for (int mi = 0; mi < 2; mi++) {
                    hmma(acc[mi][2 * np],     ah[mi], bh);
                    hmma(acc[mi][2 * np + 1], ah[mi], bh + 2);
                    hmma(acc[mi][2 * np],     ah[mi], bl);
                    hmma(acc[mi][2 * np + 1], ah[mi], bl + 2);
                    if (MODE == 3) {
                        hmma(acc[mi][2 * np],     al[mi], bh);
                        hmma(acc[mi][2 * np + 1], al[mi], bh + 2);
                    }
                }
            }
        }
    };

    // ---- prologue: fill stages 0,1,2 ----
    float4 f[AIT];
#pragma unroll
    for (int p = 0; p < NSTG - 1; p++) {
        if (p < NT) {
            if (MODE == 3) { ldgA(p, f); stsA(p, f); } else { issueA2(p); }
            issueB(p);
        }
        cp_commit();
    }
    cp_wait2();
    __syncthreads();

    // ---- mainloop: prefetch distance 3, wait_group 2 ----
    for (int kt = 0; kt < NT; kt++) {
        const bool pf = (kt + NSTG - 1 < NT);
        if (MODE == 3 && pf) ldgA(kt + NSTG - 1, f);   // LDG hidden under MMA
        if (pf) { if (MODE == 2) issueA2(kt + NSTG - 1); issueB(kt + NSTG - 1); }
        cp_commit();
        compute(kt % NSTG);
        if (MODE == 3 && pf) stsA(kt + NSTG - 1, f);   // convert + store after MMA
        cp_wait2();
        __syncthreads();
    }

    // ---- epilogue ----
    float* Cz = C + (size_t)blockIdx.z * M * Ntot;
#pragma unroll
    for (int mi = 0; mi < 2; mi++) {
        const int row = rowBase + wm * 32 + mi * 16 + (lane >> 2);
#pragma unroll
        for (int nj = 0; nj < NJ; nj++) {
            const int col = colBase + wn * NCOL + nj * 8 + (lane & 3) * 2;
            *(float2*)(Cz + (size_t)row * Ntot + col) =
                make_float2(acc[mi][nj][0], acc[mi][nj][1]);
            *(float2*)(Cz + (size_t)(row + 8) * Ntot + col) =
                make_float2(acc[mi][nj][2], acc[mi][nj][3]);
        }
    }
}

// =========================== small kernels ==================================
__global__ void split_bf16(const float* __restrict__ x,
                           __nv_bfloat16* __restrict__ hi,
                           __nv_bfloat16* __restrict__ lo, int n4)
{
    const int i = blockIdx.x * blockDim.x + threadIdx.x;
    if (i >= n4) return;
    float4 v = ((const float4*)x)[i];
    uint2 h, l;
    split4(v, h, l);
    ((uint2*)hi)[i] = h;
    ((uint2*)lo)[i] = l;
}

// reduce basal split-K partials + precompute mb(t) recurrence in one pass
__global__ void reduce_basal_mb()
{
    const int i = blockIdx.x * blockDim.x + threadIdx.x;   // over NB*NF
    if (i >= NB * NF) return;
    float mb = 0.f;
#pragma unroll
    for (int t = 0; t < TSTEPS; t++) {
        const int e = t * NB * NF + i;
        float s = 0.f;
#pragma unroll
        for (int p = 0; p < KSB; p++) s += g_bpart[(size_t)p * (TSTEPS * NB * NF) + e];
        mb += (s - mb) * 0.5f;
        g_mball[e] = mb;
    }
}

// ---- mc_all: whole MC-neuron time recurrence, elementwise, ONE launch ------
__global__ void mc_all()
{
    const int i = blockIdx.x * blockDim.x + threadIdx.x;   // over NBS*NF/4
    if (i >= NBS * NF / 4) return;
    const int e = i * 4;
    const int f = e & (NF - 1);
    const int b = e >> 14;                                 // e / (NS*NF)

    float4 mav = make_float4(0.f, 0.f, 0.f, 0.f);
    float4 msv = make_float4(0.f, 0.f, 0.f, 0.f);

#pragma unroll
    for (int t = 0; t < TSTEPS; t++) {
        float4 ap  = ((const float4*)(g_apical + (size_t)t * NBS * NF))[i];
        float4 mbv = *(const float4*)(g_mball + t * NB * NF + b * NF + f);
        float4 spv;

        mav.x += (ap.x - mav.x) * 0.5f;
        msv.x += (mav.x + mbv.x - msv.x) * 0.5f;
        spv.x = (msv.x > 1.0f) ? 1.f : 0.f;  msv.x *= (1.f - spv.x);

        mav.y += (ap.y - mav.y) * 0.5f;
        msv.y += (mav.y + mbv.y - msv.y) * 0.5f;
        spv.y = (msv.y > 1.0f) ? 1.f : 0.f;  msv.y *= (1.f - spv.y);

        mav.z += (ap.z - mav.z) * 0.5f;
        msv.z += (mav.z + mbv.z - msv.z) * 0.5f;
        spv.z = (msv.z > 1.0f) ? 1.f : 0.f;  msv.z *= (1.f - spv.z);

        mav.w += (ap.w - mav.w) * 0.5f;
        msv.w += (mav.w + mbv.w - msv.w) * 0.5f;
        spv.w = (msv.w > 1.0f) ? 1.f : 0.f;  msv.w *= (1.f - spv.w);

        __nv_bfloat162* sp = (__nv_bfloat162*)(g_spall + (size_t)t * NBS * NF + e);
        sp[0] = __halves2bfloat162(__float2bfloat16(spv.x), __float2bfloat16(spv.y));
        sp[1] = __halves2bfloat162(__float2bfloat16(spv.z), __float2bfloat16(spv.w));
    }
}

// ---- lif_all: LIF recurrence (ml in regs) + readout + finalize, ONE launch -
__global__ void lif_all(const float* __restrict__ b1, const float* __restrict__ W2,
                        const float* __restrict__ b2, float* __restrict__ out)
{
    const int gw   = (blockIdx.x * blockDim.x + threadIdx.x) >> 5;  // row bs
    const int lane = threadIdx.x & 31;
    if (gw >= NBS) return;

    float ml[NH / 32];
#pragma unroll
    for (int j = 0; j < NH / 32; j++) ml[j] = 0.f;
    float a[NL];
#pragma unroll
    for (int l = 0; l < NL; l++) a[l] = 0.f;

    for (int t = 0; t < TSTEPS; t++) {
        const float* hrow = g_hall + ((size_t)t * NBS + gw) * NH;
#pragma unroll
        for (int j = 0; j < NH / 32; j++) {
            const int k = j * 32 + lane;
            const float h = b1[k] + hrow[k];
            float m = ml[j];
            m += (h - m) * 0.5f;
            const float s = (m > 0.5f) ? 1.f : 0.f;
            ml[j] = m * (1.f - s);
            if (s != 0.f) {
#pragma unroll
                for (int l = 0; l < NL; l++) a[l] += W2[l * NH + k];
            }
        }
    }
#pragma unroll
    for (int l = 0; l < NL; l++) {
#pragma unroll
        for (int o = 16; o; o >>= 1) a[l] += __shfl_xor_sync(0xffffffffu, a[l], o);
    }
    if (lane == 0) {
        const int b = gw >> 5;          // / NS
        const int sdx = gw & 31;        // % NS
#pragma unroll
        for (int l = 0; l < NL; l++)
            out[b * NL * NS + l * NS + sdx] = a[l] * (1.f / TSTEPS) + b2[l];
    }
}

// ---------------------------------------------------------------------------
extern "C" void kernel_launch(void* const* d_in, const int* in_sizes, int n_in,
                              void* d_out, int out_size)
{
    (void)in_sizes; (void)n_in; (void)out_size;
    const float* se = (const float*)d_in[0];
    const float* te = (const float*)d_in[1];
    const float* Wb = (const float*)d_in[2];
    const float* Wa = (const float*)d_in[3];
    const float* W1 = (const float*)d_in[4];
    const float* b1 = (const float*)d_in[5];
    const float* W2 = (const float*)d_in[6];
    const float* b2 = (const float*)d_in[7];
    float* out = (float*)d_out;

    float *apical, *bpart, *hall;
    __nv_bfloat16 *Wah, *Wal, *Wbh, *Wbl, *W1h, *W1l, *spall;
    cudaGetSymbolAddress((void**)&apical, g_apical);
    cudaGetSymbolAddress((void**)&bpart,  g_bpart);
    cudaGetSymbolAddress((void**)&hall,   g_hall);
    cudaGetSymbolAddress((void**)&Wah,    g_Wah);
    cudaGetSymbolAddress((void**)&Wal,    g_Wal);
    cudaGetSymbolAddress((void**)&Wbh,    g_Wbh);
    cudaGetSymbolAddress((void**)&Wbl,    g_Wbl);
    cudaGetSymbolAddress((void**)&W1h,    g_W1h);
    cudaGetSymbolAddress((void**)&W1l,    g_W1l);
    cudaGetSymbolAddress((void**)&spall,  g_spall);

    // smem: MODE3/BM64 stage = (2*64*32 + 2*128*32)*2B = 24KB; x4 = 98304
    //       MODE2/BM64 stage  = (64*32 + 2*128*32)*2B  = 20KB; x4 = 81920
    const int SMEM_M3 = (2 * 64 * BKT + 2 * 128 * BKT) * 2 * NSTG;   // 98304
    const int SMEM_M2 = (64 * BKT + 2 * 128 * BKT) * 2 * NSTG;       // 81920
    cudaFuncSetAttribute((const void*)hmma_fused<3, 64>,
                         cudaFuncAttributeMaxDynamicSharedMemorySize, SMEM_M3);
    cudaFuncSetAttribute((const void*)hmma_fused<2, 64>,
                         cudaFuncAttributeMaxDynamicSharedMemorySize, SMEM_M2);

    // weight hi/lo splits (te/se split in-kernel)
    split_bf16<<<(NF * NK / 4 + 255) / 256, 256>>>(Wa, Wah, Wal, NF * NK / 4);
    split_bf16<<<(NF * NK / 4 + 255) / 256, 256>>>(Wb, Wbh, Wbl, NF * NK / 4);
    split_bf16<<<(NH * NF / 4 + 255) / 256, 256>>>(W1, W1h, W1l, NH * NF / 4);

    // basal: fp32-A fused-split HMMA BM=64, split-K=7
    hmma_fused<3, 64><<<dim3(NF / 128, (TSTEPS * NB) / 64, KSB), 256, SMEM_M3>>>(
        se, Wbh, Wbl, KCH_B, NK, NF, bpart, TSTEPS * NB);
    reduce_basal_mb<<<(NB * NF + 255) / 256, 256>>>();

    // apical: fp32-A fused-split HMMA BM=64, M=16384 N=512 K=3136
    hmma_fused<3, 64><<<dim3(NF / 128, (TSTEPS * NBS) / 64, 1), 256, SMEM_M3>>>(
        te, Wah, Wal, NK, NK, NF, apical, TSTEPS * NBS);

    // MC neuron: all 8 steps in one elementwise pass (state in registers)
    mc_all<<<(NBS * NF / 4 + 255) / 256, 256>>>();

    // h for ALL steps: one batched GEMM, M=16384 K=512 N=512 (2 products)
    hmma_fused<2, 64><<<dim3(NH / 128, (TSTEPS * NBS) / 64, 1), 256, SMEM_M2>>>(
        spall, W1h, W1l, NF, NF, NH, hall, TSTEPS * NBS);

    // LIF + readout + finalize: one launch, ml in registers
    lif_all<<<(NBS * 32 + 255) / 256, 256>>>(b1, W2, b2, out);
}